// round 5
// baseline (speedup 1.0000x reference)
#include <cuda_runtime.h>

// Reference collapses: only diagonal of the RBF self-Gram matrix reaches the
// output. For the diagonal, sqdist[i,i] = xn - 2*xn + xn == 0.0f exactly in
// fp32 (same value xn = X[i]^2 appears in all three terms), so
// K[i,i] = exp(-gamma*0) = 1.0f bitwise. The N^2 GEMM + exp are dead code.
//
// out[i] = sum_h relu(diag_i * W1[h] + b1[h]) * W2[h] + b2
//
// Inputs (metadata order): X[16384], gamma[1], W1[32], b1[32], W2[32], b2[1]
// Output: float32 [16384]
//
// Vectorized 4-wide: 4096 threads, 16 CTAs. Since sq == 0 for every element,
// the MLP result is shared across the 4 lanes of each thread's vector.

__global__ void qkr_kernel_v4(const float4* __restrict__ X4,
                              const float*  __restrict__ gamma,
                              const float*  __restrict__ W1,
                              const float*  __restrict__ b1,
                              const float*  __restrict__ W2,
                              const float*  __restrict__ b2,
                              float4* __restrict__ out4,
                              int n4)
{
    int i = blockIdx.x * blockDim.x + threadIdx.x;
    if (i >= n4) return;

    // Reference-faithful diagonal (propagates NaN/Inf from X exactly like the
    // reference would; for finite x, sq == 0.0f and k == 1.0f).
    float4 xv = X4[i];
    float xn = xv.x * xv.x;
    float sq = (xn - 2.0f * xn) + xn;
    float k  = __expf(-gamma[0] * sq);

    float acc = 0.0f;
    #pragma unroll
    for (int h = 0; h < 32; ++h) {
        float v = fmaf(k, W1[h], b1[h]);   // warp-uniform broadcast loads
        v = fmaxf(v, 0.0f);
        acc = fmaf(v, W2[h], acc);
    }
    float r = acc + b2[0];

    out4[i] = make_float4(r, r, r, r);
}

extern "C" void kernel_launch(void* const* d_in, const int* in_sizes, int n_in,
                              void* d_out, int out_size)
{
    const float* X     = (const float*)d_in[0];
    const float* gamma = (const float*)d_in[1];
    const float* W1    = (const float*)d_in[2];
    const float* b1    = (const float*)d_in[3];
    const float* W2    = (const float*)d_in[4];
    const float* b2    = (const float*)d_in[5];
    float* out = (float*)d_out;

    int n4 = out_size / 4;                       // 4096
    const int threads = 256;
    int blocks = (n4 + threads - 1) / threads;   // 16
    qkr_kernel_v4<<<blocks, threads>>>((const float4*)X, gamma, W1, b1, W2, b2,
                                       (float4*)out, n4);
}

// round 7
// speedup vs baseline: 1.0667x; 1.0667x over previous
#include <cuda_runtime.h>

// The reference's N^2 RBF Gram matrix is dead code: only its diagonal reaches
// the output, and for a self-kernel the fp32 diagonal distance is exactly
// x_norm - 2*x_norm + x_norm == 0.0f (the same fp32 value appears in all three
// terms), so K[i,i] = exp(-gamma * 0) bitwise. X itself never affects the
// output for finite inputs; every output element is the identical scalar
//   r = sum_h relu(exp(-gamma*0) * W1[h] + b1[h]) * W2[h] + b2.
//
// Inputs (metadata order): X[16384], gamma[1], W1[32], b1[32], W2[32], b2[1]
// Output: float32 [16384]
//
// 4096 threads (16 CTAs x 256): each computes r from the 97-float weight set
// (vectorized: 24 x LDG.128, all warp-uniform/L1-broadcast) and writes one
// STG.128 of the broadcast result.

__global__ void qkr_kernel_v5(const float*  __restrict__ gamma,
                              const float4* __restrict__ W1v,   // 8 x float4
                              const float4* __restrict__ b1v,   // 8 x float4
                              const float4* __restrict__ W2v,   // 8 x float4
                              const float*  __restrict__ b2,
                              float4* __restrict__ out4,
                              int n4)
{
    int i = blockIdx.x * blockDim.x + threadIdx.x;
    if (i >= n4) return;

    // Reference-faithful diagonal kernel value: sqdist diagonal is exactly 0.
    float k = __expf(-gamma[0] * 0.0f);      // == 1.0f (exact unless gamma is NaN/Inf)

    // Issue all weight loads up front (independent LDG.128s), then FMA.
    float4 w1[8], bb[8], w2[8];
    #pragma unroll
    for (int j = 0; j < 8; ++j) { w1[j] = W1v[j]; bb[j] = b1v[j]; w2[j] = W2v[j]; }

    float acc = 0.0f;
    #pragma unroll
    for (int j = 0; j < 8; ++j) {
        float v;
        v = fmaxf(fmaf(k, w1[j].x, bb[j].x), 0.0f); acc = fmaf(v, w2[j].x, acc);
        v = fmaxf(fmaf(k, w1[j].y, bb[j].y), 0.0f); acc = fmaf(v, w2[j].y, acc);
        v = fmaxf(fmaf(k, w1[j].z, bb[j].z), 0.0f); acc = fmaf(v, w2[j].z, acc);
        v = fmaxf(fmaf(k, w1[j].w, bb[j].w), 0.0f); acc = fmaf(v, w2[j].w, acc);
    }
    float r = acc + b2[0];

    out4[i] = make_float4(r, r, r, r);
}

extern "C" void kernel_launch(void* const* d_in, const int* in_sizes, int n_in,
                              void* d_out, int out_size)
{
    const float* gamma = (const float*)d_in[1];
    const float* W1    = (const float*)d_in[2];
    const float* b1    = (const float*)d_in[3];
    const float* W2    = (const float*)d_in[4];
    const float* b2    = (const float*)d_in[5];
    float* out = (float*)d_out;

    int n4 = out_size / 4;                       // 4096
    const int threads = 256;
    int blocks = (n4 + threads - 1) / threads;   // 16
    qkr_kernel_v5<<<blocks, threads>>>(gamma,
                                       (const float4*)W1, (const float4*)b1,
                                       (const float4*)W2, b2,
                                       (float4*)out, n4);
}